// round 15
// baseline (speedup 1.0000x reference)
#include <cuda_runtime.h>
#include <cuda_fp16.h>

// TrainableActivation (per-channel RBF activation) on GB300 — FINAL.
// (= round 11/13 optimum, measured 20.96us twice; roofline-complete)
//
// out[n,c,h,w] = sum_{j=0..30} w[c,j] * exp(-112.5 * (x - mu_j)^2)
//
// Roofline provenance (14 rounds):
//  * Six structurally disjoint memory paths (LDG register pipeline,
//    cp.async staging, barrier-free cp.async, TMA bulk-DMA, 256-bit
//    LDG/STG, fine/coarse grids) ALL pin at 19.5-20.1us kernel time.
//  * Cache-policy deviations regress (L2 evict hints: 23.6us, st.wt: 20.4us).
//  * Occupancy 59% -> 79% (R14): duration unchanged — SM-side is not the
//    binder.
//  => kernel time == 134MB mandatory L2-traversing traffic / ~6300 B/cyc
//     full-chip LTS cap ≈ 19.5us. This kernel sits on that wall.
//  * Accuracy: 512-entry lerp LUT (interp ~1.2e-4) in fp16 (~2.1e-4)
//    -> rel_err 2.25e-4 vs the 1e-3 gate.
//
// Design:
//  * Algorithmic core: 31 __expf/element (520M exps, ~120us of MUFU) is
//    replaced by ONE smem lerp-LUT gather/element; the per-channel LUT is
//    built in-block with the Gaussian lattice recurrence (sigma == spacing:
//    g_{j+1}=g_j*r_j, r_{j+1}=r_j/e; 2 __expf + 11 fma-pairs per entry)
//    and hidden under the prologue LDG latency.
//  * 512-entry half2 (value, forward-delta) LUT, 8-way bank-replicated
//    (entry i at words 8i..8i+7; lane reads copy lane&7).
//  * grid (64,16) = 1024 blocks, launch_bounds(256,7): 148*7 >= 1024, the
//    whole grid resident in ONE wave.
//  * depth-3 register input pipeline; lerp = one fma; streaming stores.

#define NUM_CH   64
#define NUM_W    31
#define LUT_N    512
#define REP      8
#define HW       16384    // 128*128
#define NBATCH   16

#define TILE_F4       256      // float4 per tile == blockDim
#define TILES_PER_BLK 16       // one full plane: 4096 float4
#define DEPTH         3        // register pipeline depth

__global__ void __launch_bounds__(256, 7)
fused_rbf_kernel(const float4* __restrict__ x,
                 float4* __restrict__ y,
                 const float* __restrict__ w)
{
    __shared__ __align__(16) __half2 lut[LUT_N * REP];  // 16 KB, 8-way replicated
    __shared__ float fv[LUT_N + 1];                     //  2 KB raw values
    __shared__ float ws[NUM_W];

    const int c   = blockIdx.x;
    const int n   = blockIdx.y;
    const int tid = threadIdx.x;

    const int base = (n * NUM_CH + c) * (HW / 4);
    const float4* src = x + base;
    float4*       dst = y + base;

    // ---- Prologue: get DRAM going before anything else -------------------
    float4 vb[DEPTH];
#pragma unroll
    for (int t = 0; t < DEPTH; t++)
        vb[t] = src[t * TILE_F4 + tid];

    // ---- Build this channel's LUT (hides under the LDG latency) ----------
    if (tid < NUM_W) ws[tid] = w[c * NUM_W + tid];
    __syncthreads();

    // f at 513 points over [-1.5,1.5]; 11-center window + lattice recurrence
    // (sigma == spacing): g_{j+1} = g_j*r_j, r_{j+1} = r_j*e^-1.
    const float h = 3.0f / (float)(LUT_N - 1);
    for (int k = tid; k < LUT_N + 1; k += 256) {
        const float xx = fmaf((float)k, h, -1.5f);
        int j0 = (int)ceilf((xx + 1.0f) * 15.0f - 5.4f);
        j0 = min(20, max(0, j0));
        const float u0 = xx - fmaf((float)j0, 1.0f / 15.0f, -1.0f);

        float g = __expf(-112.5f * u0 * u0);
        float r = __expf(fmaf(15.0f, u0, -0.5f));
        float s = 0.0f;
#pragma unroll
        for (int m = 0; m < 11; m++) {
            s = fmaf(ws[j0 + m], g, s);
            g *= r;
            r *= 0.36787944f;    // e^-1
        }
        fv[k] = s;
    }
    __syncthreads();

    // Pack (value, forward-delta) half2; replicate 8-way:
    // entry i occupies words 8i..8i+7 (lane reads copy lane&7).
#pragma unroll
    for (int m = 0; m < LUT_N / 256; m++) {
        const int i = tid + 256 * m;
        __half2 e = __floats2half2_rn(fv[i], fv[i + 1] - fv[i]);
        const unsigned u = *reinterpret_cast<unsigned*>(&e);
        const uint4 q = make_uint4(u, u, u, u);
        reinterpret_cast<uint4*>(lut)[2 * i]     = q;
        reinterpret_cast<uint4*>(lut)[2 * i + 1] = q;
    }
    __syncthreads();   // last barrier; main loop is barrier-free

    // ---- Main loop: 16 tiles through the register pipeline ---------------
    const float INV_H = (float)(LUT_N - 1) / 3.0f;
    const float OFF   = 1.5f * INV_H;
    const float TMAX  = (float)(LUT_N - 1);

    const __half2* lp = lut + (tid & 7);

#pragma unroll
    for (int t = 0; t < TILES_PER_BLK; t++) {
        const float4 v = vb[t % DEPTH];
        if (t + DEPTH < TILES_PER_BLK)                    // refill the slot
            vb[t % DEPTH] = src[(t + DEPTH) * TILE_F4 + tid];

        float4 o;
        {
            const float tt = fminf(fmaxf(fmaf(v.x, INV_H, OFF), 0.0f), TMAX);
            const int idx = (int)tt;
            const float2 e = __half22float2(lp[idx * REP]);
            o.x = fmaf(tt - (float)idx, e.y, e.x);
        }
        {
            const float tt = fminf(fmaxf(fmaf(v.y, INV_H, OFF), 0.0f), TMAX);
            const int idx = (int)tt;
            const float2 e = __half22float2(lp[idx * REP]);
            o.y = fmaf(tt - (float)idx, e.y, e.x);
        }
        {
            const float tt = fminf(fmaxf(fmaf(v.z, INV_H, OFF), 0.0f), TMAX);
            const int idx = (int)tt;
            const float2 e = __half22float2(lp[idx * REP]);
            o.z = fmaf(tt - (float)idx, e.y, e.x);
        }
        {
            const float tt = fminf(fmaxf(fmaf(v.w, INV_H, OFF), 0.0f), TMAX);
            const int idx = (int)tt;
            const float2 e = __half22float2(lp[idx * REP]);
            o.w = fmaf(tt - (float)idx, e.y, e.x);
        }

        __stcs(dst + t * TILE_F4 + tid, o);
    }
}

// ---------------------------------------------------------------------------
// Launch: ONE kernel (graph-capturable, allocation-free, deterministic).
// ---------------------------------------------------------------------------
extern "C" void kernel_launch(void* const* d_in, const int* in_sizes, int n_in,
                              void* d_out, int out_size)
{
    const float* x = (const float*)d_in[0];   // [16, 64, 128, 128] fp32
    const float* w = (const float*)d_in[1];   // [64, 31] fp32

    fused_rbf_kernel<<<dim3(NUM_CH, NBATCH), 256>>>(
        reinterpret_cast<const float4*>(x),
        reinterpret_cast<float4*>(d_out),
        w);
}

// round 16
// speedup vs baseline: 1.0271x; 1.0271x over previous
#include <cuda_runtime.h>
#include <cuda_fp16.h>

// TrainableActivation (per-channel RBF activation) on GB300 — FINAL.
// (round 11/13 optimum; measured 20.96us twice, 21.82us once — identical
// source, so the spread is bench noise, not kernel behavior)
//
// out[n,c,h,w] = sum_{j=0..30} w[c,j] * exp(-112.5 * (x - mu_j)^2)
//
// Roofline provenance (15 rounds):
//  * Six structurally disjoint memory paths (LDG register pipeline,
//    cp.async staging, barrier-free cp.async, TMA bulk-DMA, 256-bit
//    LDG/STG, fine/coarse grids) ALL pin at 19.5-20.3us kernel time.
//  * Cache-policy deviations regress (L2 evict hints: 23.6us, st.wt: 20.4us).
//  * Occupancy 59% -> 79% (R14): duration unchanged.
//  * Identical-source resubmits spread +-0.9us: remaining deltas are noise.
//  => kernel time == 134MB mandatory L2-traversing traffic at the chip's
//     effective LTS throughput (~6.9TB/s). This kernel sits on that wall.
//  * Accuracy: 512-entry lerp LUT (interp ~1.2e-4) in fp16 (~2.1e-4)
//    -> rel_err 2.25e-4 vs the 1e-3 gate.
//
// Design:
//  * Algorithmic core: 31 __expf/element (520M exps, ~120us of MUFU) is
//    replaced by ONE smem lerp-LUT gather/element; the per-channel LUT is
//    built in-block with the Gaussian lattice recurrence (sigma == spacing:
//    g_{j+1}=g_j*r_j, r_{j+1}=r_j/e; 2 __expf + 11 fma-pairs per entry)
//    and hidden under the prologue LDG latency.
//  * 512-entry half2 (value, forward-delta) LUT, 8-way bank-replicated
//    (entry i at words 8i..8i+7; lane reads copy lane&7).
//  * grid (64,16) = 1024 blocks, launch_bounds(256,7): 148*7 >= 1024, the
//    whole grid resident in ONE wave.
//  * depth-3 register input pipeline; lerp = one fma; streaming stores.

#define NUM_CH   64
#define NUM_W    31
#define LUT_N    512
#define REP      8
#define HW       16384    // 128*128
#define NBATCH   16

#define TILE_F4       256      // float4 per tile == blockDim
#define TILES_PER_BLK 16       // one full plane: 4096 float4
#define DEPTH         3        // register pipeline depth

__global__ void __launch_bounds__(256, 7)
fused_rbf_kernel(const float4* __restrict__ x,
                 float4* __restrict__ y,
                 const float* __restrict__ w)
{
    __shared__ __align__(16) __half2 lut[LUT_N * REP];  // 16 KB, 8-way replicated
    __shared__ float fv[LUT_N + 1];                     //  2 KB raw values
    __shared__ float ws[NUM_W];

    const int c   = blockIdx.x;
    const int n   = blockIdx.y;
    const int tid = threadIdx.x;

    const int base = (n * NUM_CH + c) * (HW / 4);
    const float4* src = x + base;
    float4*       dst = y + base;

    // ---- Prologue: get DRAM going before anything else -------------------
    float4 vb[DEPTH];
#pragma unroll
    for (int t = 0; t < DEPTH; t++)
        vb[t] = src[t * TILE_F4 + tid];

    // ---- Build this channel's LUT (hides under the LDG latency) ----------
    if (tid < NUM_W) ws[tid] = w[c * NUM_W + tid];
    __syncthreads();

    // f at 513 points over [-1.5,1.5]; 11-center window + lattice recurrence
    // (sigma == spacing): g_{j+1} = g_j*r_j, r_{j+1} = r_j*e^-1.
    const float h = 3.0f / (float)(LUT_N - 1);
    for (int k = tid; k < LUT_N + 1; k += 256) {
        const float xx = fmaf((float)k, h, -1.5f);
        int j0 = (int)ceilf((xx + 1.0f) * 15.0f - 5.4f);
        j0 = min(20, max(0, j0));
        const float u0 = xx - fmaf((float)j0, 1.0f / 15.0f, -1.0f);

        float g = __expf(-112.5f * u0 * u0);
        float r = __expf(fmaf(15.0f, u0, -0.5f));
        float s = 0.0f;
#pragma unroll
        for (int m = 0; m < 11; m++) {
            s = fmaf(ws[j0 + m], g, s);
            g *= r;
            r *= 0.36787944f;    // e^-1
        }
        fv[k] = s;
    }
    __syncthreads();

    // Pack (value, forward-delta) half2; replicate 8-way:
    // entry i occupies words 8i..8i+7 (lane reads copy lane&7).
#pragma unroll
    for (int m = 0; m < LUT_N / 256; m++) {
        const int i = tid + 256 * m;
        __half2 e = __floats2half2_rn(fv[i], fv[i + 1] - fv[i]);
        const unsigned u = *reinterpret_cast<unsigned*>(&e);
        const uint4 q = make_uint4(u, u, u, u);
        reinterpret_cast<uint4*>(lut)[2 * i]     = q;
        reinterpret_cast<uint4*>(lut)[2 * i + 1] = q;
    }
    __syncthreads();   // last barrier; main loop is barrier-free

    // ---- Main loop: 16 tiles through the register pipeline ---------------
    const float INV_H = (float)(LUT_N - 1) / 3.0f;
    const float OFF   = 1.5f * INV_H;
    const float TMAX  = (float)(LUT_N - 1);

    const __half2* lp = lut + (tid & 7);

#pragma unroll
    for (int t = 0; t < TILES_PER_BLK; t++) {
        const float4 v = vb[t % DEPTH];
        if (t + DEPTH < TILES_PER_BLK)                    // refill the slot
            vb[t % DEPTH] = src[(t + DEPTH) * TILE_F4 + tid];

        float4 o;
        {
            const float tt = fminf(fmaxf(fmaf(v.x, INV_H, OFF), 0.0f), TMAX);
            const int idx = (int)tt;
            const float2 e = __half22float2(lp[idx * REP]);
            o.x = fmaf(tt - (float)idx, e.y, e.x);
        }
        {
            const float tt = fminf(fmaxf(fmaf(v.y, INV_H, OFF), 0.0f), TMAX);
            const int idx = (int)tt;
            const float2 e = __half22float2(lp[idx * REP]);
            o.y = fmaf(tt - (float)idx, e.y, e.x);
        }
        {
            const float tt = fminf(fmaxf(fmaf(v.z, INV_H, OFF), 0.0f), TMAX);
            const int idx = (int)tt;
            const float2 e = __half22float2(lp[idx * REP]);
            o.z = fmaf(tt - (float)idx, e.y, e.x);
        }
        {
            const float tt = fminf(fmaxf(fmaf(v.w, INV_H, OFF), 0.0f), TMAX);
            const int idx = (int)tt;
            const float2 e = __half22float2(lp[idx * REP]);
            o.w = fmaf(tt - (float)idx, e.y, e.x);
        }

        __stcs(dst + t * TILE_F4 + tid, o);
    }
}

// ---------------------------------------------------------------------------
// Launch: ONE kernel (graph-capturable, allocation-free, deterministic).
// ---------------------------------------------------------------------------
extern "C" void kernel_launch(void* const* d_in, const int* in_sizes, int n_in,
                              void* d_out, int out_size)
{
    const float* x = (const float*)d_in[0];   // [16, 64, 128, 128] fp32
    const float* w = (const float*)d_in[1];   // [64, 31] fp32

    fused_rbf_kernel<<<dim3(NUM_CH, NBATCH), 256>>>(
        reinterpret_cast<const float4*>(x),
        reinterpret_cast<float4*>(d_out),
        w);
}

// round 17
// speedup vs baseline: 1.0412x; 1.0137x over previous
#include <cuda_runtime.h>
#include <cuda_fp16.h>

// TrainableActivation (per-channel RBF activation) on GB300 — FINAL.
// (round 11/13 optimum; identical-source measurements: 20.96, 20.96, 21.82,
// 21.25us -> +-0.6us harness noise around a 19.7-20.3us kernel)
//
// out[n,c,h,w] = sum_{j=0..30} w[c,j] * exp(-112.5 * (x - mu_j)^2)
//
// Roofline provenance (16 rounds):
//  * Six structurally disjoint memory paths (LDG register pipeline,
//    cp.async staging, barrier-free cp.async, TMA bulk-DMA, 256-bit
//    LDG/STG, fine/coarse grids) ALL pin at 19.5-20.3us kernel time.
//  * Cache-policy deviations regress (L2 evict hints: 23.6us, st.wt: 20.4us);
//    accessPolicyWindow needs a persisting-L2 carveout, which the harness
//    forbids (device-limits guard).
//  * Occupancy 59% -> 79%: duration unchanged. SM side is not the binder.
//  => binder: ~85MB/run DRAM traffic at the achievable mixed-stream HBM
//     bandwidth (~4.2TB/s on GB300) ≈ 20us. Traffic is irreducible
//     (fp32 in, fp32 out, single pass).
//  * Accuracy: 512-entry lerp LUT (interp ~1.2e-4) in fp16 (~2.1e-4)
//    -> rel_err 2.25e-4 vs the 1e-3 gate.
//
// Design:
//  * Algorithmic core: 31 __expf/element (520M exps, ~120us of MUFU) is
//    replaced by ONE smem lerp-LUT gather/element; the per-channel LUT is
//    built in-block with the Gaussian lattice recurrence (sigma == spacing:
//    g_{j+1}=g_j*r_j, r_{j+1}=r_j/e; 2 __expf + 11 fma-pairs per entry)
//    and hidden under the prologue LDG latency.
//  * 512-entry half2 (value, forward-delta) LUT, 8-way bank-replicated
//    (entry i at words 8i..8i+7; lane reads copy lane&7).
//  * grid (64,16) = 1024 blocks, launch_bounds(256,7): 148*7 >= 1024, the
//    whole grid resident in ONE wave.
//  * depth-3 register input pipeline; lerp = one fma; streaming stores.

#define NUM_CH   64
#define NUM_W    31
#define LUT_N    512
#define REP      8
#define HW       16384    // 128*128
#define NBATCH   16

#define TILE_F4       256      // float4 per tile == blockDim
#define TILES_PER_BLK 16       // one full plane: 4096 float4
#define DEPTH         3        // register pipeline depth

__global__ void __launch_bounds__(256, 7)
fused_rbf_kernel(const float4* __restrict__ x,
                 float4* __restrict__ y,
                 const float* __restrict__ w)
{
    __shared__ __align__(16) __half2 lut[LUT_N * REP];  // 16 KB, 8-way replicated
    __shared__ float fv[LUT_N + 1];                     //  2 KB raw values
    __shared__ float ws[NUM_W];

    const int c   = blockIdx.x;
    const int n   = blockIdx.y;
    const int tid = threadIdx.x;

    const int base = (n * NUM_CH + c) * (HW / 4);
    const float4* src = x + base;
    float4*       dst = y + base;

    // ---- Prologue: get DRAM going before anything else -------------------
    float4 vb[DEPTH];
#pragma unroll
    for (int t = 0; t < DEPTH; t++)
        vb[t] = src[t * TILE_F4 + tid];

    // ---- Build this channel's LUT (hides under the LDG latency) ----------
    if (tid < NUM_W) ws[tid] = w[c * NUM_W + tid];
    __syncthreads();

    // f at 513 points over [-1.5,1.5]; 11-center window + lattice recurrence
    // (sigma == spacing): g_{j+1} = g_j*r_j, r_{j+1} = r_j*e^-1.
    const float h = 3.0f / (float)(LUT_N - 1);
    for (int k = tid; k < LUT_N + 1; k += 256) {
        const float xx = fmaf((float)k, h, -1.5f);
        int j0 = (int)ceilf((xx + 1.0f) * 15.0f - 5.4f);
        j0 = min(20, max(0, j0));
        const float u0 = xx - fmaf((float)j0, 1.0f / 15.0f, -1.0f);

        float g = __expf(-112.5f * u0 * u0);
        float r = __expf(fmaf(15.0f, u0, -0.5f));
        float s = 0.0f;
#pragma unroll
        for (int m = 0; m < 11; m++) {
            s = fmaf(ws[j0 + m], g, s);
            g *= r;
            r *= 0.36787944f;    // e^-1
        }
        fv[k] = s;
    }
    __syncthreads();

    // Pack (value, forward-delta) half2; replicate 8-way:
    // entry i occupies words 8i..8i+7 (lane reads copy lane&7).
#pragma unroll
    for (int m = 0; m < LUT_N / 256; m++) {
        const int i = tid + 256 * m;
        __half2 e = __floats2half2_rn(fv[i], fv[i + 1] - fv[i]);
        const unsigned u = *reinterpret_cast<unsigned*>(&e);
        const uint4 q = make_uint4(u, u, u, u);
        reinterpret_cast<uint4*>(lut)[2 * i]     = q;
        reinterpret_cast<uint4*>(lut)[2 * i + 1] = q;
    }
    __syncthreads();   // last barrier; main loop is barrier-free

    // ---- Main loop: 16 tiles through the register pipeline ---------------
    const float INV_H = (float)(LUT_N - 1) / 3.0f;
    const float OFF   = 1.5f * INV_H;
    const float TMAX  = (float)(LUT_N - 1);

    const __half2* lp = lut + (tid & 7);

#pragma unroll
    for (int t = 0; t < TILES_PER_BLK; t++) {
        const float4 v = vb[t % DEPTH];
        if (t + DEPTH < TILES_PER_BLK)                    // refill the slot
            vb[t % DEPTH] = src[(t + DEPTH) * TILE_F4 + tid];

        float4 o;
        {
            const float tt = fminf(fmaxf(fmaf(v.x, INV_H, OFF), 0.0f), TMAX);
            const int idx = (int)tt;
            const float2 e = __half22float2(lp[idx * REP]);
            o.x = fmaf(tt - (float)idx, e.y, e.x);
        }
        {
            const float tt = fminf(fmaxf(fmaf(v.y, INV_H, OFF), 0.0f), TMAX);
            const int idx = (int)tt;
            const float2 e = __half22float2(lp[idx * REP]);
            o.y = fmaf(tt - (float)idx, e.y, e.x);
        }
        {
            const float tt = fminf(fmaxf(fmaf(v.z, INV_H, OFF), 0.0f), TMAX);
            const int idx = (int)tt;
            const float2 e = __half22float2(lp[idx * REP]);
            o.z = fmaf(tt - (float)idx, e.y, e.x);
        }
        {
            const float tt = fminf(fmaxf(fmaf(v.w, INV_H, OFF), 0.0f), TMAX);
            const int idx = (int)tt;
            const float2 e = __half22float2(lp[idx * REP]);
            o.w = fmaf(tt - (float)idx, e.y, e.x);
        }

        __stcs(dst + t * TILE_F4 + tid, o);
    }
}

// ---------------------------------------------------------------------------
// Launch: ONE kernel (graph-capturable, allocation-free, deterministic).
// ---------------------------------------------------------------------------
extern "C" void kernel_launch(void* const* d_in, const int* in_sizes, int n_in,
                              void* d_out, int out_size)
{
    const float* x = (const float*)d_in[0];   // [16, 64, 128, 128] fp32
    const float* w = (const float*)d_in[1];   // [64, 31] fp32

    fused_rbf_kernel<<<dim3(NUM_CH, NBATCH), 256>>>(
        reinterpret_cast<const float4*>(x),
        reinterpret_cast<float4*>(d_out),
        w);
}